// round 9
// baseline (speedup 1.0000x reference)
#include <cuda_runtime.h>
#include <cuda_fp16.h>
#include <cstdint>

#define BB 8
#define CC 256
#define SS 2304

#define BM 128
#define BN 128
#define BKK 32
#define KITERS (CC / BKK)   // 8
#define NSTAGE 4

// Padded SMEM row: 32 fp16 = 64B data, padded to 80B (conflict-free ldmatrix)
#define ROWB 80
#define A_TILE (BM * ROWB)               // 10240
#define B_TILE (BN * ROWB)               // 10240
#define OFF_A 0
#define OFF_B A_TILE
#define STG_BYTES (A_TILE + B_TILE)           // 20480
#define SMEM_TOTAL (NSTAGE * STG_BYTES)       // 81920 (x2 CTAs = 160KB/SM)

// ---------------- scratch (__device__ globals; no cudaMalloc allowed) ------
__device__ __half g_A[(size_t)BB * SS * CC];
__device__ __half g_B[(size_t)BB * SS * CC];
__device__ float g_part[2][8][BB * SS];   // per-32ch partial sum of squares

// ---------------- PTX helpers (base ISA only) -------------------------------
__device__ __forceinline__ uint32_t smem_u32(const void* p) {
    uint32_t a;
    asm("{ .reg .u64 t; cvta.to.shared.u64 t, %1; cvt.u32.u64 %0, t; }"
        : "=r"(a) : "l"(p));
    return a;
}
__device__ __forceinline__ void cpasync16(uint32_t dst, const void* src) {
    asm volatile("cp.async.cg.shared.global [%0], [%1], 16;"
                 :: "r"(dst), "l"(src) : "memory");
}
#define CP_COMMIT() asm volatile("cp.async.commit_group;" ::: "memory")
#define CP_WAIT(n)  asm volatile("cp.async.wait_group %0;" :: "n"(n) : "memory")

__device__ __forceinline__ void ldsm_x4(uint32_t* r, uint32_t addr) {
    asm volatile("ldmatrix.sync.aligned.m8n8.x4.shared.b16 {%0,%1,%2,%3}, [%4];"
                 : "=r"(r[0]), "=r"(r[1]), "=r"(r[2]), "=r"(r[3]) : "r"(addr));
}
__device__ __forceinline__ void mma16816(float* d, const uint32_t* a,
                                         uint32_t b0, uint32_t b1) {
    asm volatile(
        "mma.sync.aligned.m16n8k16.row.col.f32.f16.f16.f32 "
        "{%0,%1,%2,%3}, {%4,%5,%6,%7}, {%8,%9}, {%0,%1,%2,%3};"
        : "+f"(d[0]), "+f"(d[1]), "+f"(d[2]), "+f"(d[3])
        : "r"(a[0]), "r"(a[1]), "r"(a[2]), "r"(a[3]), "r"(b0), "r"(b1));
}

// ---------------------------------------------------------------------------
// Kernel 1: transpose + fp16 convert + fused partial sum of squares
// ---------------------------------------------------------------------------
__global__ void prep_kernel(const float* __restrict__ src,
                            const float* __restrict__ dst) {
    __shared__ float tile[32][33];
    int z = blockIdx.z;
    int b = z >> 1, which = z & 1;
    const float* in = which ? dst : src;
    __half* outp = which ? g_B : g_A;
    int c0 = blockIdx.y * 32, s0 = blockIdx.x * 32;
    int tx = threadIdx.x & 31, ty = threadIdx.x >> 5;

    const float* p = in + (size_t)b * CC * SS;
#pragma unroll
    for (int i = 0; i < 4; ++i)
        tile[ty + i * 8][tx] = p[(size_t)(c0 + ty + i * 8) * SS + s0 + tx];
    __syncthreads();

    // phase 2: 256 threads = 32 s x 8 channel-groups (4 ch each)
    const int s_local = threadIdx.x >> 3;
    const int cg = threadIdx.x & 7;
    float v0 = tile[cg * 4 + 0][s_local];
    float v1 = tile[cg * 4 + 1][s_local];
    float v2 = tile[cg * 4 + 2][s_local];
    float v3 = tile[cg * 4 + 3][s_local];

    __half2 h01 = __floats2half2_rn(v0, v1);
    __half2 h23 = __floats2half2_rn(v2, v3);
    uint2 pack = make_uint2(*(uint32_t*)&h01, *(uint32_t*)&h23);
    *(uint2*)&outp[((size_t)b * SS + s0 + s_local) * CC + c0 + cg * 4] = pack;

    float sq = v0 * v0 + v1 * v1 + v2 * v2 + v3 * v3;
    sq += __shfl_xor_sync(0xffffffffu, sq, 1);
    sq += __shfl_xor_sync(0xffffffffu, sq, 2);
    sq += __shfl_xor_sync(0xffffffffu, sq, 4);
    if (cg == 0)
        g_part[which][blockIdx.y][b * SS + s0 + s_local] = sq;
}

// ---------------------------------------------------------------------------
// Kernel 2: HMMA GEMM, occupancy 2. CTA 128x128, BK=32, 4-stage cp.async.
//   8 warps (4m x 2n), warp tile 32x64. fp16 x fp16 -> fp32 accumulate.
//   Inverse norms computed in-kernel from g_part into SMEM (combine fused).
// ---------------------------------------------------------------------------
__global__ void __launch_bounds__(256, 2)
corr_mma_kernel(float* __restrict__ out) {
    extern __shared__ char smem[];
    uint32_t sb = smem_u32(smem);

    const int tid  = threadIdx.x;
    const int lane = tid & 31;
    const int wid  = tid >> 5;
    const int b  = blockIdx.z;
    const int m0 = blockIdx.y * BM;
    const int n0 = blockIdx.x * BN;

    const char* gA = (const char*)(g_A + (size_t)b * SS * CC);
    const char* gB = (const char*)(g_B + (size_t)b * SS * CC);

    // Stage loader: A 128 rows + B 128 rows, 4x16B chunks per row. 4 cp/thread.
    auto load_stage = [&](int st, int kt) {
        uint32_t sbase = sb + (uint32_t)st * STG_BYTES;
        int c0 = kt * BKK;
#pragma unroll
        for (int i = 0; i < 2; ++i) {
            int u = tid + i * 256;             // [0,512)
            int row = u >> 2, ch = u & 3;
            size_t goA = ((size_t)(m0 + row) * CC + c0) * 2 + ch * 16;
            size_t goB = ((size_t)(n0 + row) * CC + c0) * 2 + ch * 16;
            uint32_t so = (uint32_t)(row * ROWB + ch * 16);
            cpasync16(sbase + OFF_A + so, gA + goA);
            cpasync16(sbase + OFF_B + so, gB + goB);
        }
    };

    load_stage(0, 0); CP_COMMIT();
    load_stage(1, 1); CP_COMMIT();
    load_stage(2, 2); CP_COMMIT();

    float acc[2][8][4];
#pragma unroll
    for (int i = 0; i < 2; ++i)
#pragma unroll
        for (int j = 0; j < 8; ++j)
#pragma unroll
            for (int k = 0; k < 4; ++k) acc[i][j][k] = 0.0f;

    const int wm = wid & 3;    // m strip (32 rows)
    const int wn = wid >> 2;   // n strip (64 cols)

    const uint32_t aOff = (uint32_t)((wm * 32 + (lane & 15)) * ROWB + (lane >> 4) * 16);
    const uint32_t bRow = (uint32_t)(wn * 64 + (lane & 7) + ((lane >> 4) << 3));
    const uint32_t bOff = bRow * ROWB + ((lane >> 3) & 1) * 16;

    for (int kt = 0; kt < KITERS; ++kt) {
        CP_WAIT(2);
        __syncthreads();
        if (kt + 3 < KITERS) load_stage((kt + 3) % NSTAGE, kt + 3);
        CP_COMMIT();

        const uint32_t sbase = sb + (uint32_t)(kt % NSTAGE) * STG_BYTES;
#pragma unroll
        for (int ks = 0; ks < 2; ++ks) {
            const uint32_t koff = (uint32_t)ks * 32;   // k16 = 32 bytes

            uint32_t a[2][4], bh[4][4];
#pragma unroll
            for (int mt = 0; mt < 2; ++mt)
                ldsm_x4(a[mt], sbase + OFF_A + aOff + (uint32_t)mt * 16 * ROWB + koff);
#pragma unroll
            for (int p = 0; p < 4; ++p)
                ldsm_x4(bh[p], sbase + OFF_B + bOff + (uint32_t)p * 16 * ROWB + koff);
#pragma unroll
            for (int mt = 0; mt < 2; ++mt)
#pragma unroll
                for (int p = 0; p < 4; ++p) {
                    mma16816(acc[mt][2 * p],     a[mt], bh[p][0], bh[p][1]);
                    mma16816(acc[mt][2 * p + 1], a[mt], bh[p][2], bh[p][3]);
                }
        }
    }

    // ---- fused combine: inverse norms into SMEM (reuse stage-0 tile space)
    CP_WAIT(0);
    __syncthreads();
    float* sInv = (float*)smem;           // [0..127]=inv_src(m), [128..255]=inv_dst(n)
    {
        int which = (tid >= 128) ? 1 : 0;
        int base  = which ? n0 : m0;
        int i = (tid & 127);
        float s = 0.0f;
#pragma unroll
        for (int cb = 0; cb < 8; ++cb)
            s += g_part[which][cb][b * SS + base + i];
        sInv[tid] = rsqrtf(s);
    }
    __syncthreads();

    // ---- epilogue: scale by inverse norms, ReLU, float2 stores
#pragma unroll
    for (int mt = 0; mt < 2; ++mt) {
#pragma unroll
        for (int h = 0; h < 2; ++h) {
            int ml = wm * 32 + mt * 16 + (lane >> 2) + h * 8;
            float invs = sInv[ml];
            float* orow = out + ((size_t)b * SS + m0 + ml) * SS + n0;
#pragma unroll
            for (int nt = 0; nt < 8; ++nt) {
                int n = wn * 64 + nt * 8 + (lane & 3) * 2;
                float2 o;
                o.x = fmaxf(acc[mt][nt][h * 2 + 0] * invs * sInv[128 + n], 0.0f);
                o.y = fmaxf(acc[mt][nt][h * 2 + 1] * invs * sInv[128 + n + 1], 0.0f);
                *(float2*)&orow[n] = o;
            }
        }
    }
}

// ---------------------------------------------------------------------------
extern "C" void kernel_launch(void* const* d_in, const int* in_sizes, int n_in,
                              void* d_out, int out_size) {
    const float* src = (const float*)d_in[0];
    const float* dst = (const float*)d_in[1];
    float* out = (float*)d_out;

    cudaFuncSetAttribute(corr_mma_kernel,
                         cudaFuncAttributeMaxDynamicSharedMemorySize, SMEM_TOTAL);

    prep_kernel<<<dim3(SS / 32, CC / 32, 2 * BB), 256>>>(src, dst);
    corr_mma_kernel<<<dim3(SS / BN, SS / BM, BB), 256, SMEM_TOTAL>>>(out);
}

// round 10
// speedup vs baseline: 1.4098x; 1.4098x over previous
#include <cuda_runtime.h>
#include <cuda_fp16.h>
#include <cstdint>

#define BB 8
#define CC 256
#define SS 2304

#define BM 128
#define BN 128
#define BKK 32
#define KITERS (CC / BKK)   // 8
#define NSTAGE 4

// Padded SMEM row: 32 fp16 = 64B data, padded to 80B (conflict-free ldmatrix)
#define ROWB 80
#define A_TILE (BM * ROWB)               // 10240
#define B_TILE (BN * ROWB)               // 10240
#define OFF_A 0
#define OFF_B A_TILE
#define STG_BYTES (A_TILE + B_TILE)           // 20480
#define SMEM_TOTAL (NSTAGE * STG_BYTES)       // 81920 (x2 CTAs = 160KB/SM)

// ---------------- scratch (__device__ globals; no cudaMalloc allowed) ------
__device__ __half g_A[(size_t)BB * SS * CC];
__device__ __half g_B[(size_t)BB * SS * CC];
__device__ float g_part[2][8][BB * SS];   // per-32ch partial sum of squares
__device__ float g_inv_src[BB * SS];
__device__ float g_inv_dst[BB * SS];

// ---------------- PTX helpers (base ISA only) -------------------------------
__device__ __forceinline__ uint32_t smem_u32(const void* p) {
    uint32_t a;
    asm("{ .reg .u64 t; cvta.to.shared.u64 t, %1; cvt.u32.u64 %0, t; }"
        : "=r"(a) : "l"(p));
    return a;
}
__device__ __forceinline__ void cpasync16(uint32_t dst, const void* src) {
    asm volatile("cp.async.cg.shared.global [%0], [%1], 16;"
                 :: "r"(dst), "l"(src) : "memory");
}
#define CP_COMMIT() asm volatile("cp.async.commit_group;" ::: "memory")
#define CP_WAIT(n)  asm volatile("cp.async.wait_group %0;" :: "n"(n) : "memory")

__device__ __forceinline__ void ldsm_x4(uint32_t* r, uint32_t addr) {
    asm volatile("ldmatrix.sync.aligned.m8n8.x4.shared.b16 {%0,%1,%2,%3}, [%4];"
                 : "=r"(r[0]), "=r"(r[1]), "=r"(r[2]), "=r"(r[3]) : "r"(addr));
}
__device__ __forceinline__ void mma16816(float* d, const uint32_t* a,
                                         uint32_t b0, uint32_t b1) {
    asm volatile(
        "mma.sync.aligned.m16n8k16.row.col.f32.f16.f16.f32 "
        "{%0,%1,%2,%3}, {%4,%5,%6,%7}, {%8,%9}, {%0,%1,%2,%3};"
        : "+f"(d[0]), "+f"(d[1]), "+f"(d[2]), "+f"(d[3])
        : "r"(a[0]), "r"(a[1]), "r"(a[2]), "r"(a[3]), "r"(b0), "r"(b1));
}

// ---------------------------------------------------------------------------
// Kernel 1: transpose + fp16 convert + fused partial sum of squares
// ---------------------------------------------------------------------------
__global__ void prep_kernel(const float* __restrict__ src,
                            const float* __restrict__ dst) {
    __shared__ float tile[32][33];
    int z = blockIdx.z;
    int b = z >> 1, which = z & 1;
    const float* in = which ? dst : src;
    __half* outp = which ? g_B : g_A;
    int c0 = blockIdx.y * 32, s0 = blockIdx.x * 32;
    int tx = threadIdx.x & 31, ty = threadIdx.x >> 5;

    const float* p = in + (size_t)b * CC * SS;
#pragma unroll
    for (int i = 0; i < 4; ++i)
        tile[ty + i * 8][tx] = p[(size_t)(c0 + ty + i * 8) * SS + s0 + tx];
    __syncthreads();

    // phase 2: 256 threads = 32 s x 8 channel-groups (4 ch each)
    const int s_local = threadIdx.x >> 3;
    const int cg = threadIdx.x & 7;
    float v0 = tile[cg * 4 + 0][s_local];
    float v1 = tile[cg * 4 + 1][s_local];
    float v2 = tile[cg * 4 + 2][s_local];
    float v3 = tile[cg * 4 + 3][s_local];

    __half2 h01 = __floats2half2_rn(v0, v1);
    __half2 h23 = __floats2half2_rn(v2, v3);
    uint2 pack = make_uint2(*(uint32_t*)&h01, *(uint32_t*)&h23);
    *(uint2*)&outp[((size_t)b * SS + s0 + s_local) * CC + c0 + cg * 4] = pack;

    float sq = v0 * v0 + v1 * v1 + v2 * v2 + v3 * v3;
    sq += __shfl_xor_sync(0xffffffffu, sq, 1);
    sq += __shfl_xor_sync(0xffffffffu, sq, 2);
    sq += __shfl_xor_sync(0xffffffffu, sq, 4);
    if (cg == 0)
        g_part[which][blockIdx.y][b * SS + s0 + s_local] = sq;
}

// ---------------------------------------------------------------------------
// Kernel 2: combine partials -> inverse norms
// ---------------------------------------------------------------------------
__global__ void combine_kernel() {
    int idx = blockIdx.x * blockDim.x + threadIdx.x;
    const int total = BB * SS;
    int which = (idx >= total) ? 1 : 0;
    int i = idx - which * total;
    float s = 0.0f;
#pragma unroll
    for (int cb = 0; cb < 8; ++cb) s += g_part[which][cb][i];
    float r = rsqrtf(s);
    if (which) g_inv_dst[i] = r; else g_inv_src[i] = r;
}

// ---------------------------------------------------------------------------
// Kernel 3: HMMA GEMM, occupancy 2. CTA 128x128, BK=32, 4-stage cp.async.
//   8 warps (4m x 2n), warp tile 32x64. fp16 x fp16 -> fp32 accumulate.
// ---------------------------------------------------------------------------
__global__ void __launch_bounds__(256, 2)
corr_mma_kernel(float* __restrict__ out) {
    extern __shared__ char smem[];
    uint32_t sb = smem_u32(smem);

    const int tid  = threadIdx.x;
    const int lane = tid & 31;
    const int wid  = tid >> 5;
    const int b  = blockIdx.z;
    const int m0 = blockIdx.y * BM;
    const int n0 = blockIdx.x * BN;

    const char* gA = (const char*)(g_A + (size_t)b * SS * CC);
    const char* gB = (const char*)(g_B + (size_t)b * SS * CC);

    // Stage loader: A 128 rows + B 128 rows, 4x16B chunks per row. 4 cp/thread.
    auto load_stage = [&](int st, int kt) {
        uint32_t sbase = sb + (uint32_t)st * STG_BYTES;
        int c0 = kt * BKK;
#pragma unroll
        for (int i = 0; i < 2; ++i) {
            int u = tid + i * 256;             // [0,512)
            int row = u >> 2, ch = u & 3;
            size_t goA = ((size_t)(m0 + row) * CC + c0) * 2 + ch * 16;
            size_t goB = ((size_t)(n0 + row) * CC + c0) * 2 + ch * 16;
            uint32_t so = (uint32_t)(row * ROWB + ch * 16);
            cpasync16(sbase + OFF_A + so, gA + goA);
            cpasync16(sbase + OFF_B + so, gB + goB);
        }
    };

    load_stage(0, 0); CP_COMMIT();
    load_stage(1, 1); CP_COMMIT();
    load_stage(2, 2); CP_COMMIT();

    float acc[2][8][4];
#pragma unroll
    for (int i = 0; i < 2; ++i)
#pragma unroll
        for (int j = 0; j < 8; ++j)
#pragma unroll
            for (int k = 0; k < 4; ++k) acc[i][j][k] = 0.0f;

    const int wm = wid & 3;    // m strip (32 rows)
    const int wn = wid >> 2;   // n strip (64 cols)

    const uint32_t aOff = (uint32_t)((wm * 32 + (lane & 15)) * ROWB + (lane >> 4) * 16);
    const uint32_t bRow = (uint32_t)(wn * 64 + (lane & 7) + ((lane >> 4) << 3));
    const uint32_t bOff = bRow * ROWB + ((lane >> 3) & 1) * 16;

    for (int kt = 0; kt < KITERS; ++kt) {
        CP_WAIT(2);
        __syncthreads();
        if (kt + 3 < KITERS) load_stage((kt + 3) % NSTAGE, kt + 3);
        CP_COMMIT();

        const uint32_t sbase = sb + (uint32_t)(kt % NSTAGE) * STG_BYTES;
#pragma unroll
        for (int ks = 0; ks < 2; ++ks) {
            const uint32_t koff = (uint32_t)ks * 32;   // k16 = 32 bytes

            uint32_t a[2][4], bh[4][4];
#pragma unroll
            for (int mt = 0; mt < 2; ++mt)
                ldsm_x4(a[mt], sbase + OFF_A + aOff + (uint32_t)mt * 16 * ROWB + koff);
#pragma unroll
            for (int p = 0; p < 4; ++p)
                ldsm_x4(bh[p], sbase + OFF_B + bOff + (uint32_t)p * 16 * ROWB + koff);
#pragma unroll
            for (int mt = 0; mt < 2; ++mt)
#pragma unroll
                for (int p = 0; p < 4; ++p) {
                    mma16816(acc[mt][2 * p],     a[mt], bh[p][0], bh[p][1]);
                    mma16816(acc[mt][2 * p + 1], a[mt], bh[p][2], bh[p][3]);
                }
        }
    }

    // ---- epilogue: scale by inverse norms, ReLU, float2 stores
    const float* invd = &g_inv_dst[b * SS + n0];
#pragma unroll
    for (int mt = 0; mt < 2; ++mt) {
#pragma unroll
        for (int h = 0; h < 2; ++h) {
            int m = m0 + wm * 32 + mt * 16 + (lane >> 2) + h * 8;
            float invs = g_inv_src[b * SS + m];
            float* orow = out + ((size_t)b * SS + m) * SS + n0;
#pragma unroll
            for (int nt = 0; nt < 8; ++nt) {
                int n = wn * 64 + nt * 8 + (lane & 3) * 2;
                float2 o;
                o.x = fmaxf(acc[mt][nt][h * 2 + 0] * invs * invd[n], 0.0f);
                o.y = fmaxf(acc[mt][nt][h * 2 + 1] * invs * invd[n + 1], 0.0f);
                *(float2*)&orow[n] = o;
            }
        }
    }
}

// ---------------------------------------------------------------------------
extern "C" void kernel_launch(void* const* d_in, const int* in_sizes, int n_in,
                              void* d_out, int out_size) {
    const float* src = (const float*)d_in[0];
    const float* dst = (const float*)d_in[1];
    float* out = (float*)d_out;

    cudaFuncSetAttribute(corr_mma_kernel,
                         cudaFuncAttributeMaxDynamicSharedMemorySize, SMEM_TOTAL);

    prep_kernel<<<dim3(SS / 32, CC / 32, 2 * BB), 256>>>(src, dst);
    combine_kernel<<<2 * BB * SS / 256, 256>>>();
    corr_mma_kernel<<<dim3(SS / BN, SS / BM, BB), 256, SMEM_TOTAL>>>(out);
}

// round 11
// speedup vs baseline: 1.5441x; 1.0952x over previous
#include <cuda_runtime.h>
#include <cuda_fp16.h>
#include <cstdint>

#define BB 8
#define CC 256
#define SS 2304

#define BM 128
#define BN 128
#define BKK 32
#define KITERS (CC / BKK)   // 8
#define NSTAGE 4

// Padded SMEM row: 32 fp16 = 64B data, padded to 80B (conflict-free ldmatrix)
#define ROWB 80
#define A_TILE (BM * ROWB)               // 10240
#define B_TILE (BN * ROWB)               // 10240
#define OFF_A 0
#define OFF_B A_TILE
#define STG_BYTES (A_TILE + B_TILE)           // 20480
#define SMEM_TOTAL (NSTAGE * STG_BYTES)       // 81920 (x2 CTAs = 160KB/SM)

// ---------------- scratch (__device__ globals; no cudaMalloc allowed) ------
// Pre-normalized fp16 operands, K-major [B, S, C]
__device__ __half g_A[(size_t)BB * SS * CC];
__device__ __half g_B[(size_t)BB * SS * CC];

// ---------------- PTX helpers (base ISA only) -------------------------------
__device__ __forceinline__ uint32_t smem_u32(const void* p) {
    uint32_t a;
    asm("{ .reg .u64 t; cvta.to.shared.u64 t, %1; cvt.u32.u64 %0, t; }"
        : "=r"(a) : "l"(p));
    return a;
}
__device__ __forceinline__ void cpasync16(uint32_t dst, const void* src) {
    asm volatile("cp.async.cg.shared.global [%0], [%1], 16;"
                 :: "r"(dst), "l"(src) : "memory");
}
#define CP_COMMIT() asm volatile("cp.async.commit_group;" ::: "memory")
#define CP_WAIT(n)  asm volatile("cp.async.wait_group %0;" :: "n"(n) : "memory")

__device__ __forceinline__ void ldsm_x4(uint32_t* r, uint32_t addr) {
    asm volatile("ldmatrix.sync.aligned.m8n8.x4.shared.b16 {%0,%1,%2,%3}, [%4];"
                 : "=r"(r[0]), "=r"(r[1]), "=r"(r[2]), "=r"(r[3]) : "r"(addr));
}
__device__ __forceinline__ void mma16816(float* d, const uint32_t* a,
                                         uint32_t b0, uint32_t b1) {
    asm volatile(
        "mma.sync.aligned.m16n8k16.row.col.f32.f16.f16.f32 "
        "{%0,%1,%2,%3}, {%4,%5,%6,%7}, {%8,%9}, {%0,%1,%2,%3};"
        : "+f"(d[0]), "+f"(d[1]), "+f"(d[2]), "+f"(d[3])
        : "r"(a[0]), "r"(a[1]), "r"(a[2]), "r"(a[3]), "r"(b0), "r"(b1));
}

// ---------------------------------------------------------------------------
// Kernel 1: transpose + normalize + fp16 convert (norm fused in-CTA).
//   Each CTA: one 32-s strip x all 256 channels of one (b, which).
//   grid (SS/32, 2*BB), block 256.
// ---------------------------------------------------------------------------
__global__ void __launch_bounds__(256)
prep_kernel(const float* __restrict__ src, const float* __restrict__ dst) {
    __shared__ float tile[CC][33];        // 256 x 33 floats = 33792 B
    const int z = blockIdx.y;
    const int b = z >> 1, which = z & 1;
    const float* in = which ? dst : src;
    __half* outp = which ? g_B : g_A;
    const int s0 = blockIdx.x * 32;
    const int tx = threadIdx.x & 31, ty = threadIdx.x >> 5;

    const float* p = in + (size_t)b * CC * SS + s0 + tx;
#pragma unroll
    for (int i = 0; i < 32; ++i)
        tile[ty + i * 8][tx] = p[(size_t)(ty + i * 8) * SS];
    __syncthreads();

    // thread (s_local = tid>>3, cg = tid&7) owns channels {32t + cg*4 + j}
    const int s_local = threadIdx.x >> 3;
    const int cg = threadIdx.x & 7;

    float v[32];
    float sq = 0.0f;
#pragma unroll
    for (int t = 0; t < 8; ++t)
#pragma unroll
        for (int j = 0; j < 4; ++j) {
            float x = tile[t * 32 + cg * 4 + j][s_local];
            v[t * 4 + j] = x;
            sq = fmaf(x, x, sq);
        }
    sq += __shfl_xor_sync(0xffffffffu, sq, 1);
    sq += __shfl_xor_sync(0xffffffffu, sq, 2);
    sq += __shfl_xor_sync(0xffffffffu, sq, 4);
    const float inv = rsqrtf(sq);

    __half* orow = outp + ((size_t)b * SS + s0 + s_local) * CC + cg * 4;
#pragma unroll
    for (int t = 0; t < 8; ++t) {
        __half2 h01 = __floats2half2_rn(v[t * 4 + 0] * inv, v[t * 4 + 1] * inv);
        __half2 h23 = __floats2half2_rn(v[t * 4 + 2] * inv, v[t * 4 + 3] * inv);
        uint2 pack = make_uint2(*(uint32_t*)&h01, *(uint32_t*)&h23);
        *(uint2*)&orow[t * 32] = pack;
    }
}

// ---------------------------------------------------------------------------
// Kernel 2: HMMA GEMM, occupancy 2. CTA 128x128, BK=32, 4-stage cp.async.
//   8 warps (4m x 2n), warp tile 32x64. fp16 x fp16 -> fp32 accumulate.
//   Operands pre-normalized -> epilogue is just ReLU + store.
// ---------------------------------------------------------------------------
__global__ void __launch_bounds__(256, 2)
corr_mma_kernel(float* __restrict__ out) {
    extern __shared__ char smem[];
    uint32_t sb = smem_u32(smem);

    const int tid  = threadIdx.x;
    const int lane = tid & 31;
    const int wid  = tid >> 5;
    const int b  = blockIdx.z;
    const int m0 = blockIdx.y * BM;
    const int n0 = blockIdx.x * BN;

    const char* gA = (const char*)(g_A + (size_t)b * SS * CC);
    const char* gB = (const char*)(g_B + (size_t)b * SS * CC);

    // Stage loader: A 128 rows + B 128 rows, 4x16B chunks per row. 4 cp/thread.
    auto load_stage = [&](int st, int kt) {
        uint32_t sbase = sb + (uint32_t)st * STG_BYTES;
        int c0 = kt * BKK;
#pragma unroll
        for (int i = 0; i < 2; ++i) {
            int u = tid + i * 256;             // [0,512)
            int row = u >> 2, ch = u & 3;
            size_t goA = ((size_t)(m0 + row) * CC + c0) * 2 + ch * 16;
            size_t goB = ((size_t)(n0 + row) * CC + c0) * 2 + ch * 16;
            uint32_t so = (uint32_t)(row * ROWB + ch * 16);
            cpasync16(sbase + OFF_A + so, gA + goA);
            cpasync16(sbase + OFF_B + so, gB + goB);
        }
    };

    load_stage(0, 0); CP_COMMIT();
    load_stage(1, 1); CP_COMMIT();
    load_stage(2, 2); CP_COMMIT();

    float acc[2][8][4];
#pragma unroll
    for (int i = 0; i < 2; ++i)
#pragma unroll
        for (int j = 0; j < 8; ++j)
#pragma unroll
            for (int k = 0; k < 4; ++k) acc[i][j][k] = 0.0f;

    const int wm = wid & 3;    // m strip (32 rows)
    const int wn = wid >> 2;   // n strip (64 cols)

    const uint32_t aOff = (uint32_t)((wm * 32 + (lane & 15)) * ROWB + (lane >> 4) * 16);
    const uint32_t bRow = (uint32_t)(wn * 64 + (lane & 7) + ((lane >> 4) << 3));
    const uint32_t bOff = bRow * ROWB + ((lane >> 3) & 1) * 16;

    for (int kt = 0; kt < KITERS; ++kt) {
        CP_WAIT(2);
        __syncthreads();
        if (kt + 3 < KITERS) load_stage((kt + 3) % NSTAGE, kt + 3);
        CP_COMMIT();

        const uint32_t sbase = sb + (uint32_t)(kt % NSTAGE) * STG_BYTES;
#pragma unroll
        for (int ks = 0; ks < 2; ++ks) {
            const uint32_t koff = (uint32_t)ks * 32;   // k16 = 32 bytes

            uint32_t a[2][4], bh[4][4];
#pragma unroll
            for (int mt = 0; mt < 2; ++mt)
                ldsm_x4(a[mt], sbase + OFF_A + aOff + (uint32_t)mt * 16 * ROWB + koff);
#pragma unroll
            for (int p = 0; p < 4; ++p)
                ldsm_x4(bh[p], sbase + OFF_B + bOff + (uint32_t)p * 16 * ROWB + koff);
#pragma unroll
            for (int mt = 0; mt < 2; ++mt)
#pragma unroll
                for (int p = 0; p < 4; ++p) {
                    mma16816(acc[mt][2 * p],     a[mt], bh[p][0], bh[p][1]);
                    mma16816(acc[mt][2 * p + 1], a[mt], bh[p][2], bh[p][3]);
                }
        }
    }

    // ---- epilogue: ReLU + float2 stores (operands pre-normalized)
#pragma unroll
    for (int mt = 0; mt < 2; ++mt) {
#pragma unroll
        for (int h = 0; h < 2; ++h) {
            int m = m0 + wm * 32 + mt * 16 + (lane >> 2) + h * 8;
            float* orow = out + ((size_t)b * SS + m) * SS + n0;
#pragma unroll
            for (int nt = 0; nt < 8; ++nt) {
                int n = wn * 64 + nt * 8 + (lane & 3) * 2;
                float2 o;
                o.x = fmaxf(acc[mt][nt][h * 2 + 0], 0.0f);
                o.y = fmaxf(acc[mt][nt][h * 2 + 1], 0.0f);
                *(float2*)&orow[n] = o;
            }
        }
    }
}

// ---------------------------------------------------------------------------
extern "C" void kernel_launch(void* const* d_in, const int* in_sizes, int n_in,
                              void* d_out, int out_size) {
    const float* src = (const float*)d_in[0];
    const float* dst = (const float*)d_in[1];
    float* out = (float*)d_out;

    cudaFuncSetAttribute(corr_mma_kernel,
                         cudaFuncAttributeMaxDynamicSharedMemorySize, SMEM_TOTAL);

    prep_kernel<<<dim3(SS / 32, 2 * BB), 256>>>(src, dst);
    corr_mma_kernel<<<dim3(SS / BN, SS / BM, BB), 256, SMEM_TOTAL>>>(out);
}